// round 8
// baseline (speedup 1.0000x reference)
#include <cuda_runtime.h>
#include <cuda_bf16.h>

// QuantumCBOW: B=16384, S=10, DIM=8, TRIL=36.
// R8 = R7 with the blowup fixed: um = u - |dd| clamped >= 0 (fp cancellation
// could make it ~-|dd|*2e-7, and s2*rsqrt(1e-30) then exploded to |s|~1e6).
//  * 3 Jacobi sweeps
//  * division-free rotation (parallel sqrt-via-rsqrt chains)
//  * double-buffered token-row prefetch + early target-row loads

#define QC_DIM  8
#define QC_TRIL 36
#define QC_S    10

__device__ __forceinline__ constexpr int sidx(int i, int j) { return i * (i + 1) / 2 + j; }
__device__ __forceinline__ constexpr int symi(int i, int j) { return (i >= j) ? sidx(i, j) : sidx(j, i); }

// Load one 144B embedding row as 9 float4.
#define LDROW(dst, tok) do {                                                   \
    const float4* _r = reinterpret_cast<const float4*>(emb + (long)(tok) * QC_TRIL); \
    _Pragma("unroll")                                                          \
    for (int _v = 0; _v < 9; _v++) dst[_v] = _r[_v];                           \
} while (0)

// Accumulate wgt * normalized-density(buf) into acc[36] (lower-tri storage).
__device__ __forceinline__ void accum_density(const float4 buf[9], float* acc, float wgt) {
    float L[QC_TRIL];
#pragma unroll
    for (int v = 0; v < 9; v++) {
        L[4 * v + 0] = buf[v].x; L[4 * v + 1] = buf[v].y;
        L[4 * v + 2] = buf[v].z; L[4 * v + 3] = buf[v].w;
    }
#pragma unroll
    for (int i = 0; i < QC_DIM; i++) {
        const int d = sidx(i, i);
        L[d] = fmaxf(L[d], 1e-4f);
    }
    float tr = 0.f;
#pragma unroll
    for (int i = 0; i < QC_TRIL; i++) tr = fmaf(L[i], L[i], tr);
    const float inv = wgt * __fdividef(1.0f, tr + 1.7e-5f);
#pragma unroll
    for (int i = 0; i < QC_DIM; i++) {
#pragma unroll
        for (int j = 0; j <= i; j++) {
            float s = 0.f;
#pragma unroll
            for (int k = 0; k <= j; k++)
                s = fmaf(L[sidx(i, k)], L[sidx(j, k)], s);
            if (i == j) s += 2e-6f;  // eps + corr
            acc[sidx(i, j)] = fmaf(s, inv, acc[sidx(i, j)]);
        }
    }
}

// Division-free packed-symmetric Jacobi rotation on W[36], pair (p,q), p<q.
//   u = sqrt(dd^2 + (2apq)^2); c = sqrt((u+|dd|)/(2u)); |s| = sqrt((u-|dd|)/(2u));
//   sgn(s) = sgn(apq*dd); diag shift h = t*apq = copysign((u-|dd|)/2, dd).
//   um clamped >= 0: u is rsqrt-derived (~2^-22 rel err), so u-|dd| can come
//   out fp-negative when apq~0, and a negative s2 through s2*rsqrt blows up.
#define JROT(p, q) do {                                                        \
    const float apq = W[sidx(q, p)];                                           \
    const float dd  = W[sidx(q, q)] - W[sidx(p, p)];                           \
    const float a2  = 2.0f * apq;                                              \
    const float vv  = fmaf(dd, dd, fmaf(a2, a2, 1e-30f));                      \
    const float r   = rsqrtf(vv);                                              \
    const float u   = vv * r;                                                  \
    const float ad  = fabsf(dd);                                               \
    const float rh  = 0.5f * r;                                                \
    const float um  = fmaxf(u - ad, 0.0f);            /* math: >=0 always */   \
    const float c2  = (u + ad) * rh;                                           \
    const float s2  = um * rh;                                                 \
    const float c   = c2 * rsqrtf(c2);                 /* c2 >= 0.5 */         \
    const float sm  = s2 * rsqrtf(fmaxf(s2, 1e-30f));  /* s2 may be 0 */       \
    const float s   = copysignf(sm, apq * dd);                                 \
    const float h   = copysignf(0.5f * um, dd);                                \
    W[sidx(p, p)] = W[sidx(p, p)] - h;                                         \
    W[sidx(q, q)] = W[sidx(q, q)] + h;                                         \
    W[sidx(q, p)] = 0.0f;                                                      \
    _Pragma("unroll")                                                          \
    for (int k = 0; k < QC_DIM; k++) {                                         \
        if (k != p && k != q) {                                                \
            const float akp = W[symi(k, p)];                                   \
            const float akq = W[symi(k, q)];                                   \
            W[symi(k, p)] = fmaf(c, akp, -s * akq);                            \
            W[symi(k, q)] = fmaf(s, akp,  c * akq);                            \
        }                                                                      \
    }                                                                          \
} while (0)

__global__ void __launch_bounds__(32, 8)
qcbow_kernel(const int* __restrict__ contexts,
             const int* __restrict__ targets,
             const float* __restrict__ emb,
             float* __restrict__ out,
             int B) {
    const int b = blockIdx.x * blockDim.x + threadIdx.x;
    if (b >= B) return;

    // ---- token ids (row is 8B-aligned: 10 ints = 5 x int2) ----
    int toks[QC_S];
    {
        const int2* c2 = reinterpret_cast<const int2*>(contexts + b * QC_S);
#pragma unroll
        for (int v = 0; v < 5; v++) {
            const int2 t = c2[v];
            toks[2 * v] = t.x; toks[2 * v + 1] = t.y;
        }
    }
    const int tgt = targets[b];

    // ---- early loads: target row + first context row ----
    float4 Tbuf[9];
    LDROW(Tbuf, tgt);
    float4 Abuf[9], Bbuf[9];
    LDROW(Abuf, toks[0]);

    // ---- context rho: double-buffered pipeline over 10 tokens ----
    float ctx[QC_TRIL];
#pragma unroll
    for (int i = 0; i < QC_TRIL; i++) ctx[i] = 0.f;
    float cnt = 0.f;
#pragma unroll
    for (int t = 0; t < QC_S; t++) {
        if (t + 1 < QC_S) {
            if (t & 1) { LDROW(Abuf, toks[t + 1]); }
            else       { LDROW(Bbuf, toks[t + 1]); }
        }
        const float m = (toks[t] != 0) ? 1.0f : 0.0f;
        cnt += m;
        accum_density((t & 1) ? Bbuf : Abuf, ctx, m);
    }
    {
        const float ic = __fdividef(1.0f, cnt);  // cnt==0 -> inf, matches ref 0/0
#pragma unroll
        for (int i = 0; i < QC_TRIL; i++) ctx[i] *= ic;
    }

    // ---- in-place Cholesky of (ctx + 1e-6 I): ctx becomes C with C C^T ----
#pragma unroll
    for (int j = 0; j < QC_DIM; j++) {
        float d = ctx[sidx(j, j)] + 1e-6f;
#pragma unroll
        for (int k = 0; k < j; k++) d = fmaf(-ctx[sidx(j, k)], ctx[sidx(j, k)], d);
        d = fmaxf(d, 1e-14f);
        const float icjj = rsqrtf(d);
        ctx[sidx(j, j)] = d * icjj;
#pragma unroll
        for (int i = j + 1; i < QC_DIM; i++) {
            float v = ctx[sidx(i, j)];
#pragma unroll
            for (int k = 0; k < j; k++) v = fmaf(-ctx[sidx(i, k)], ctx[sidx(j, k)], v);
            ctx[sidx(i, j)] = v * icjj;
        }
    }

    // ---- target sigma (loads long since landed) ----
    float sig[QC_TRIL];
#pragma unroll
    for (int i = 0; i < QC_TRIL; i++) sig[i] = 0.f;
    accum_density(Tbuf, sig, 1.0f);

    // ---- W = C^T * sigma * C, packed lower-tri (eig(W) = eig((ctx+eps I) sigma)) ----
    float W[QC_TRIL];
#pragma unroll
    for (int j = 0; j < QC_DIM; j++) {
        float tj[QC_DIM];  // column j of T = sigma * C
#pragma unroll
        for (int i = 0; i < QC_DIM; i++) {
            float s = 0.f;
#pragma unroll
            for (int k = j; k < QC_DIM; k++)      // C[k][j] nonzero for k>=j
                s = fmaf(sig[symi(i, k)], ctx[sidx(k, j)], s);
            tj[i] = s;
        }
#pragma unroll
        for (int i = 0; i <= j; i++) {            // W[i][j], i<=j -> store at sidx(j,i)
            float s = 0.f;
#pragma unroll
            for (int k = i; k < QC_DIM; k++)      // C[k][i] nonzero for k>=i
                s = fmaf(ctx[sidx(k, i)], tj[k], s);
            W[sidx(j, i)] = s;
        }
    }

    // ---- eigenvalues-only packed Jacobi, round-robin, 3 sweeps ----
#pragma unroll 1
    for (int sweep = 0; sweep < 3; sweep++) {
        JROT(0, 7); JROT(1, 6); JROT(2, 5); JROT(3, 4);
        JROT(1, 7); JROT(0, 2); JROT(3, 6); JROT(4, 5);
        JROT(2, 7); JROT(1, 3); JROT(0, 4); JROT(5, 6);
        JROT(3, 7); JROT(2, 4); JROT(1, 5); JROT(0, 6);
        JROT(4, 7); JROT(3, 5); JROT(2, 6); JROT(0, 1);
        JROT(5, 7); JROT(4, 6); JROT(0, 3); JROT(1, 2);
        JROT(6, 7); JROT(0, 5); JROT(1, 4); JROT(2, 3);
    }

    // ---- f = sum sqrt(|eig| + eps); out = -log(clip(f)) ----
    float f = 0.f;
#pragma unroll
    for (int i = 0; i < QC_DIM; i++) {
        const float x = fabsf(W[sidx(i, i)]) + 1e-6f;
        f = fmaf(x, rsqrtf(x), f);   // sqrt(x) = x * rsqrt(x), x >= 1e-6
    }
    f = fminf(f, 1.0f);
    f = fmaxf(f, 1e-8f);
    out[b] = -logf(f);
}

extern "C" void kernel_launch(void* const* d_in, const int* in_sizes, int n_in,
                              void* d_out, int out_size) {
    const int*   contexts = (const int*)d_in[0];   // [B, 10] int32
    const int*   targets  = (const int*)d_in[1];   // [B] int32
    const float* emb      = (const float*)d_in[2]; // [V, 36] float32
    float*       out      = (float*)d_out;         // [B] float32
    const int B = in_sizes[1];
    const int threads = 32;                         // 512 blocks -> all 148 SMs busy
    const int blocks = (B + threads - 1) / threads;
    qcbow_kernel<<<blocks, threads>>>(contexts, targets, emb, out, B);
}

// round 9
// speedup vs baseline: 1.3433x; 1.3433x over previous
#include <cuda_runtime.h>
#include <cuda_bf16.h>

// QuantumCBOW: B=16384, S=10, DIM=8, TRIL=36.
// R9 = R6 exactly (best verified config: packed symmetric Jacobi, fdividef
// rotation, 512x32 launch, int2 token prefetch, 154 regs / issue 31.5%)
// with ONE change: 3 Jacobi sweeps instead of 4.
// (R7/R8's division-free rotation + triple row-buffer prefetch regressed:
//  alu-pipe chain + 108 regs of live buffers -> issue 18.8%, reverted.)

#define QC_DIM  8
#define QC_TRIL 36
#define QC_S    10

__device__ __forceinline__ constexpr int sidx(int i, int j) { return i * (i + 1) / 2 + j; }
__device__ __forceinline__ constexpr int symi(int i, int j) { return (i >= j) ? sidx(i, j) : sidx(j, i); }

// Accumulate wgt * normalized-density(row) into acc[36] (lower-tri storage).
__device__ __forceinline__ void add_density(const float* __restrict__ row, float* acc, float wgt) {
    float L[QC_TRIL];
    const float4* r4 = reinterpret_cast<const float4*>(row);  // 36*4B rows, 16B aligned
#pragma unroll
    for (int v = 0; v < 9; v++) {
        float4 t = r4[v];
        L[4 * v + 0] = t.x; L[4 * v + 1] = t.y;
        L[4 * v + 2] = t.z; L[4 * v + 3] = t.w;
    }
#pragma unroll
    for (int i = 0; i < QC_DIM; i++) {
        const int d = sidx(i, i);
        L[d] = fmaxf(L[d], 1e-4f);
    }
    float tr = 0.f;
#pragma unroll
    for (int i = 0; i < QC_TRIL; i++) tr = fmaf(L[i], L[i], tr);
    const float inv = wgt * __fdividef(1.0f, tr + 1.7e-5f);
#pragma unroll
    for (int i = 0; i < QC_DIM; i++) {
#pragma unroll
        for (int j = 0; j <= i; j++) {
            float s = 0.f;
#pragma unroll
            for (int k = 0; k <= j; k++)
                s = fmaf(L[sidx(i, k)], L[sidx(j, k)], s);
            if (i == j) s += 2e-6f;  // eps + corr
            acc[sidx(i, j)] = fmaf(s, inv, acc[sidx(i, j)]);
        }
    }
}

// Packed-symmetric branchless Jacobi rotation on W[36], pair (p,q), p<q.
// Closed-form diagonal: app' = app - t*apq, aqq' = aqq + t*apq, apq' = 0.
#define JROT(p, q) do {                                                        \
    const float apq = W[sidx(q, p)];                                           \
    const float dd  = W[sidx(q, q)] - W[sidx(p, p)];                           \
    const float a2  = 2.0f * apq;                                              \
    const float vv  = fmaf(dd, dd, fmaf(a2, a2, 1e-30f));                      \
    const float u   = vv * rsqrtf(vv);                                         \
    const float t   = __fdividef(a2 * copysignf(1.0f, dd), fabsf(dd) + u);     \
    const float c   = rsqrtf(fmaf(t, t, 1.0f));                                \
    const float s   = t * c;                                                   \
    W[sidx(p, p)] = fmaf(-t, apq, W[sidx(p, p)]);                              \
    W[sidx(q, q)] = fmaf( t, apq, W[sidx(q, q)]);                              \
    W[sidx(q, p)] = 0.0f;                                                      \
    _Pragma("unroll")                                                          \
    for (int k = 0; k < QC_DIM; k++) {                                         \
        if (k != p && k != q) {                                                \
            const float akp = W[symi(k, p)];                                   \
            const float akq = W[symi(k, q)];                                   \
            W[symi(k, p)] = fmaf(c, akp, -s * akq);                            \
            W[symi(k, q)] = fmaf(s, akp,  c * akq);                            \
        }                                                                      \
    }                                                                          \
} while (0)

__global__ void __launch_bounds__(32, 8)
qcbow_kernel(const int* __restrict__ contexts,
             const int* __restrict__ targets,
             const float* __restrict__ emb,
             float* __restrict__ out,
             int B) {
    const int b = blockIdx.x * blockDim.x + threadIdx.x;
    if (b >= B) return;

    // ---- prefetch all token ids (row is 8B-aligned: 10 ints = 5 x int2) ----
    int toks[QC_S];
    {
        const int2* c2 = reinterpret_cast<const int2*>(contexts + b * QC_S);
#pragma unroll
        for (int v = 0; v < 5; v++) {
            const int2 t = c2[v];
            toks[2 * v] = t.x; toks[2 * v + 1] = t.y;
        }
    }
    const int tgt = targets[b];

    // ---- context rho: branchless masked mean of per-token densities ----
    float ctx[QC_TRIL];
#pragma unroll
    for (int i = 0; i < QC_TRIL; i++) ctx[i] = 0.f;
    float cnt = 0.f;
#pragma unroll 2
    for (int t = 0; t < QC_S; t++) {
        const float m = (toks[t] != 0) ? 1.0f : 0.0f;
        cnt += m;
        add_density(emb + (long)toks[t] * QC_TRIL, ctx, m);
    }
    {
        const float ic = __fdividef(1.0f, cnt);  // cnt==0 -> inf, matches ref 0/0
#pragma unroll
        for (int i = 0; i < QC_TRIL; i++) ctx[i] *= ic;
    }

    // ---- in-place Cholesky of (ctx + 1e-6 I): ctx becomes C with C C^T ----
#pragma unroll
    for (int j = 0; j < QC_DIM; j++) {
        float d = ctx[sidx(j, j)] + 1e-6f;
#pragma unroll
        for (int k = 0; k < j; k++) d = fmaf(-ctx[sidx(j, k)], ctx[sidx(j, k)], d);
        d = fmaxf(d, 1e-14f);
        const float icjj = rsqrtf(d);
        ctx[sidx(j, j)] = d * icjj;
#pragma unroll
        for (int i = j + 1; i < QC_DIM; i++) {
            float v = ctx[sidx(i, j)];
#pragma unroll
            for (int k = 0; k < j; k++) v = fmaf(-ctx[sidx(i, k)], ctx[sidx(j, k)], v);
            ctx[sidx(i, j)] = v * icjj;
        }
    }

    // ---- target sigma ----
    float sig[QC_TRIL];
#pragma unroll
    for (int i = 0; i < QC_TRIL; i++) sig[i] = 0.f;
    add_density(emb + (long)tgt * QC_TRIL, sig, 1.0f);

    // ---- W = C^T * sigma * C, packed lower-tri (eig(W) = eig((ctx+eps I) sigma)) ----
    float W[QC_TRIL];
#pragma unroll
    for (int j = 0; j < QC_DIM; j++) {
        float tj[QC_DIM];  // column j of T = sigma * C
#pragma unroll
        for (int i = 0; i < QC_DIM; i++) {
            float s = 0.f;
#pragma unroll
            for (int k = j; k < QC_DIM; k++)      // C[k][j] nonzero for k>=j
                s = fmaf(sig[symi(i, k)], ctx[sidx(k, j)], s);
            tj[i] = s;
        }
#pragma unroll
        for (int i = 0; i <= j; i++) {            // W[i][j], i<=j -> store at sidx(j,i)
            float s = 0.f;
#pragma unroll
            for (int k = i; k < QC_DIM; k++)      // C[k][i] nonzero for k>=i
                s = fmaf(ctx[sidx(k, i)], tj[k], s);
            W[sidx(j, i)] = s;
        }
    }

    // ---- eigenvalues-only packed Jacobi, round-robin, 3 sweeps ----
#pragma unroll 1
    for (int sweep = 0; sweep < 3; sweep++) {
        JROT(0, 7); JROT(1, 6); JROT(2, 5); JROT(3, 4);
        JROT(1, 7); JROT(0, 2); JROT(3, 6); JROT(4, 5);
        JROT(2, 7); JROT(1, 3); JROT(0, 4); JROT(5, 6);
        JROT(3, 7); JROT(2, 4); JROT(1, 5); JROT(0, 6);
        JROT(4, 7); JROT(3, 5); JROT(2, 6); JROT(0, 1);
        JROT(5, 7); JROT(4, 6); JROT(0, 3); JROT(1, 2);
        JROT(6, 7); JROT(0, 5); JROT(1, 4); JROT(2, 3);
    }

    // ---- f = sum sqrt(|eig| + eps); out = -log(clip(f)) ----
    float f = 0.f;
#pragma unroll
    for (int i = 0; i < QC_DIM; i++) {
        const float x = fabsf(W[sidx(i, i)]) + 1e-6f;
        f = fmaf(x, rsqrtf(x), f);   // sqrt(x) = x * rsqrt(x), x >= 1e-6
    }
    f = fminf(f, 1.0f);
    f = fmaxf(f, 1e-8f);
    out[b] = -logf(f);
}

extern "C" void kernel_launch(void* const* d_in, const int* in_sizes, int n_in,
                              void* d_out, int out_size) {
    const int*   contexts = (const int*)d_in[0];   // [B, 10] int32
    const int*   targets  = (const int*)d_in[1];   // [B] int32
    const float* emb      = (const float*)d_in[2]; // [V, 36] float32
    float*       out      = (float*)d_out;         // [B] float32
    const int B = in_sizes[1];
    const int threads = 32;                         // 512 blocks -> all 148 SMs busy
    const int blocks = (B + threads - 1) / threads;
    qcbow_kernel<<<blocks, threads>>>(contexts, targets, emb, out, B);
}